// round 15
// baseline (speedup 1.0000x reference)
#include <cuda_runtime.h>
#include <cuda_fp16.h>
#include <cstdint>

#define BATCH 4
#define SEQ   4096
#define DIM   512

#define NSD (4ull*4096ull*512ull)     // 8,388,608
#define NW  (3ull*512ull*512ull)      // 786,432
#define NSS (4ull*4096ull*4096ull)    // 67,108,864

// ---------------- static scratch (allocation-free) ----------------
__device__ __half g_Xf[NSD];                 // X plain fp16
__device__ __half g_Wf[NW];                  // weights plain fp16
__device__ __half g_Qf[NSD];
__device__ __half g_Kf[NSD];
__device__ __half g_Vf[NSD];
__device__ __half g_Ph[NSS];                 // unnormalized exp(scores), fp16
__device__ float  g_Lpart[(size_t)BATCH * 32 * 128 * 32];     // [b][qt][row][kt], 2 MB
__device__ float  g_Opart[(size_t)16 * 80 * 16384];           // [b*4+nt][s][128x128], 84 MB

// ---------------- PTX helpers (compute_103-baseline ISA only) ----------------
__device__ __forceinline__ uint32_t smem_u32(const void* p) {
    uint32_t a;
    asm("{ .reg .u64 t; cvta.to.shared.u64 t, %1; cvt.u32.u64 %0, t; }" : "=r"(a) : "l"(p));
    return a;
}

__device__ __forceinline__ void cp16(uint32_t s, const void* g) {
    asm volatile("cp.async.cg.shared.global [%0], [%1], 16;" :: "r"(s), "l"(g) : "memory");
}
#define CP_COMMIT() asm volatile("cp.async.commit_group;" ::: "memory")
#define CP_WAIT(n)  asm volatile("cp.async.wait_group %0;" :: "n"(n) : "memory")

__device__ __forceinline__ void ldm4(uint32_t addr, uint32_t r[4]) {
    asm volatile("ldmatrix.sync.aligned.m8n8.x4.shared.b16 {%0,%1,%2,%3}, [%4];"
                 : "=r"(r[0]), "=r"(r[1]), "=r"(r[2]), "=r"(r[3]) : "r"(addr));
}

__device__ __forceinline__ void ldm4t(uint32_t addr, uint32_t r[4]) {
    asm volatile("ldmatrix.sync.aligned.m8n8.x4.trans.shared.b16 {%0,%1,%2,%3}, [%4];"
                 : "=r"(r[0]), "=r"(r[1]), "=r"(r[2]), "=r"(r[3]) : "r"(addr));
}

__device__ __forceinline__ void mma_hf(float* c, const uint32_t* a, uint32_t b0, uint32_t b1) {
    asm volatile(
        "mma.sync.aligned.m16n8k16.row.col.f32.f16.f16.f32 "
        "{%0,%1,%2,%3}, {%4,%5,%6,%7}, {%8,%9}, {%0,%1,%2,%3};"
        : "+f"(c[0]), "+f"(c[1]), "+f"(c[2]), "+f"(c[3])
        : "r"(a[0]), "r"(a[1]), "r"(a[2]), "r"(a[3]), "r"(b0), "r"(b1));
}

// ---------------- GEMM config ----------------
#define ROWP     144
#define TILE_B   (128 * ROWP)          // 18432
#define ROWB     272
#define TILE_BB  (64 * ROWB)           // 17408
#define OFF3_A   0
#define OFF3_B   (1 * TILE_B)
#define STAGE3_B (2 * TILE_B)          // 36864
#define SMEM_ALLOC3 (2 * STAGE3_B)     // 73728
#define OFFP_A   0
#define OFFP_B   TILE_B
#define STAGEP_B (TILE_B + TILE_BB)    // 35840
#define SMEM_ALLOCP (2 * STAGEP_B)     // 71680
#define NTHR     256

template <typename T>
__device__ __forceinline__ void fill_tile(uint32_t sb, const T* __restrict__ src,
                                          int ld, int k0, int tid) {
#pragma unroll
    for (int v = 0; v < 4; ++v) {
        int idx = v * NTHR + tid;
        int row = idx >> 3;
        int c16 = idx & 7;
        cp16(sb + row * ROWP + c16 * 16, src + (size_t)row * ld + k0 + c16 * 8);
    }
}

__device__ __forceinline__ void fill_vtile(uint32_t sb, const __half* __restrict__ src,
                                           int k0, int tid) {
#pragma unroll
    for (int v = 0; v < 4; ++v) {
        int idx = v * NTHR + tid;
        int row = idx >> 4;
        int c16 = idx & 15;
        cp16(sb + row * ROWB + c16 * 16, src + (size_t)(k0 + row) * DIM + c16 * 8);
    }
}

// ---------------- plain fp16 mainloop (proj & scores) ----------------
__device__ __forceinline__ void gemm_fp16(
    const __half* __restrict__ A, int lda,
    const __half* __restrict__ B, int ldb,
    int ktotal, float acc[4][4][4])
{
    extern __shared__ char rawsm[];
    const uint32_t smb = smem_u32(rawsm);
    const int tid  = threadIdx.x;
    const int lane = tid & 31;
    const int wid  = tid >> 5;
    const int wm   = wid >> 2;
    const int wn   = wid & 3;

#pragma unroll
    for (int i = 0; i < 4; ++i)
#pragma unroll
        for (int j = 0; j < 4; ++j)
#pragma unroll
            for (int k = 0; k < 4; ++k) acc[i][j][k] = 0.f;

    const int nch = ktotal >> 6;

    fill_tile(smb + OFF3_A, A, lda, 0, tid);
    fill_tile(smb + OFF3_B, B, ldb, 0, tid);
    CP_COMMIT();

    const uint32_t a_row_off = (uint32_t)((wm * 64 + (lane & 15)) * ROWP);
    const uint32_t b_row_off = (uint32_t)((wn * 32 + (lane & 7) + ((lane >> 3) & 1) * 8) * ROWP);
    const uint32_t k_half    = (uint32_t)(((lane >> 4) & 1) * 16);

    for (int c = 0; c < nch; ++c) {
        CP_WAIT(0);
        __syncthreads();
        if (c + 1 < nch) {
            const uint32_t nb = smb + (uint32_t)(((c + 1) & 1) * STAGE3_B);
            const int nk = (c + 1) << 6;
            fill_tile(nb + OFF3_A, A, lda, nk, tid);
            fill_tile(nb + OFF3_B, B, ldb, nk, tid);
            CP_COMMIT();
        }

        const uint32_t sb = smb + (uint32_t)((c & 1) * STAGE3_B);

#pragma unroll
        for (int ks = 0; ks < 4; ++ks) {
            const uint32_t ko = (uint32_t)(ks * 32) + k_half;

            uint32_t ra[4][4], rb[2][4];
#pragma unroll
            for (int mf = 0; mf < 4; ++mf)
                ldm4(sb + OFF3_A + a_row_off + (uint32_t)(mf * 16 * ROWP) + ko, ra[mf]);
#pragma unroll
            for (int bf = 0; bf < 2; ++bf)
                ldm4(sb + OFF3_B + b_row_off + (uint32_t)(bf * 16 * ROWP) + ko, rb[bf]);

#pragma unroll
            for (int mf = 0; mf < 4; ++mf)
#pragma unroll
                for (int bf = 0; bf < 2; ++bf) {
                    mma_hf(acc[mf][bf * 2],     ra[mf], rb[bf][0], rb[bf][2]);
                    mma_hf(acc[mf][bf * 2 + 1], ra[mf], rb[bf][1], rb[bf][3]);
                }
        }
    }
    __syncthreads();
}

// ---------------- pv mainloop: B from natural V via ldmatrix.trans ----------
__device__ __forceinline__ void gemm_fp16_pv(
    const __half* __restrict__ A, int lda,
    const __half* __restrict__ V,
    int ktotal, float acc[4][4][4])
{
    extern __shared__ char rawsm[];
    const uint32_t smb = smem_u32(rawsm);
    const int tid  = threadIdx.x;
    const int lane = tid & 31;
    const int wid  = tid >> 5;
    const int wm   = wid >> 2;
    const int wn   = wid & 3;

#pragma unroll
    for (int i = 0; i < 4; ++i)
#pragma unroll
        for (int j = 0; j < 4; ++j)
#pragma unroll
            for (int k = 0; k < 4; ++k) acc[i][j][k] = 0.f;

    const int nch = ktotal >> 6;

    fill_tile(smb + OFFP_A, A, lda, 0, tid);
    fill_vtile(smb + OFFP_B, V, 0, tid);
    CP_COMMIT();

    const uint32_t a_row_off = (uint32_t)((wm * 64 + (lane & 15)) * ROWP);
    const uint32_t k_half    = (uint32_t)(((lane >> 4) & 1) * 16);
    const uint32_t bt_off = (uint32_t)(((lane & 7) + ((lane >> 4) & 1) * 8) * ROWB
                                       + wn * 64 + ((lane >> 3) & 1) * 16);

    for (int c = 0; c < nch; ++c) {
        CP_WAIT(0);
        __syncthreads();
        if (c + 1 < nch) {
            const uint32_t nb = smb + (uint32_t)(((c + 1) & 1) * STAGEP_B);
            const int nk = (c + 1) << 6;
            fill_tile(nb + OFFP_A, A, lda, nk, tid);
            fill_vtile(nb + OFFP_B, V, nk, tid);
            CP_COMMIT();
        }

        const uint32_t sb = smb + (uint32_t)((c & 1) * STAGEP_B);

#pragma unroll
        for (int ks = 0; ks < 4; ++ks) {
            const uint32_t ko = (uint32_t)(ks * 32) + k_half;

            uint32_t ra[4][4], rb[2][4];
#pragma unroll
            for (int mf = 0; mf < 4; ++mf)
                ldm4(sb + OFFP_A + a_row_off + (uint32_t)(mf * 16 * ROWP) + ko, ra[mf]);
#pragma unroll
            for (int bf = 0; bf < 2; ++bf)
                ldm4t(sb + OFFP_B + (uint32_t)(ks * 16 * ROWB) + bt_off + (uint32_t)(bf * 32),
                      rb[bf]);

#pragma unroll
            for (int mf = 0; mf < 4; ++mf)
#pragma unroll
                for (int bf = 0; bf < 2; ++bf) {
                    mma_hf(acc[mf][bf * 2],     ra[mf], rb[bf][0], rb[bf][2]);
                    mma_hf(acc[mf][bf * 2 + 1], ra[mf], rb[bf][1], rb[bf][3]);
                }
        }
    }
    __syncthreads();
}

// ---------------- stage kernels ----------------

// X and W -> plain fp16, vectorized 4-wide, one launch
__global__ __launch_bounds__(1024) void convert_kernel(const float* __restrict__ x,
                                                       const float* __restrict__ wq,
                                                       const float* __restrict__ wk,
                                                       const float* __restrict__ wv) {
    size_t i = (size_t)blockIdx.x * blockDim.x + threadIdx.x;   // float4 index
    const size_t nx4 = NSD >> 2, nw4 = NW >> 2, nwq4 = (NW / 3) >> 2;
    if (i < nx4) {
        float4 v = reinterpret_cast<const float4*>(x)[i];
        __half2 h0 = __halves2half2(__float2half_rn(v.x), __float2half_rn(v.y));
        __half2 h1 = __halves2half2(__float2half_rn(v.z), __float2half_rn(v.w));
        reinterpret_cast<__half2*>(g_Xf)[i * 2]     = h0;
        reinterpret_cast<__half2*>(g_Xf)[i * 2 + 1] = h1;
    } else if (i < nx4 + nw4) {
        size_t j = i - nx4;
        size_t which = j / nwq4;
        size_t off   = j - which * nwq4;
        const float* src = (which == 0) ? wq : (which == 1) ? wk : wv;
        float4 v = reinterpret_cast<const float4*>(src)[off];
        __half2 h0 = __halves2half2(__float2half_rn(v.x), __float2half_rn(v.y));
        __half2 h1 = __halves2half2(__float2half_rn(v.z), __float2half_rn(v.w));
        reinterpret_cast<__half2*>(g_Wf)[j * 2]     = h0;
        reinterpret_cast<__half2*>(g_Wf)[j * 2 + 1] = h1;
    }
}

// QKV projection: grid (4 ntile, 128 mtile, 3 which)
__global__ __launch_bounds__(NTHR) void proj_kernel() {
    const int nt = blockIdx.x, mt = blockIdx.y, z = blockIdx.z;
    const __half* A = g_Xf + (size_t)mt * 128 * DIM;
    const __half* B = g_Wf + (size_t)z * DIM * DIM + (size_t)nt * 128 * DIM;

    float acc[4][4][4];
    gemm_fp16(A, DIM, B, DIM, DIM, acc);

    __half* dst0 = (z == 0) ? g_Qf : (z == 1) ? g_Kf : g_Vf;

    const int lane = threadIdx.x & 31, wid = threadIdx.x >> 5;
    const int wm = wid >> 2, wn = wid & 3;
    const int g = lane >> 2, t = lane & 3;
    const size_t rbase = (size_t)mt * 128;
    const int cbase = nt * 128 + wn * 32 + 2 * t;

#pragma unroll
    for (int mf = 0; mf < 4; ++mf) {
#pragma unroll
        for (int nf = 0; nf < 4; ++nf) {
            const int col = cbase + nf * 8;
#pragma unroll
            for (int half = 0; half < 2; ++half) {
                const int row = wm * 64 + mf * 16 + g + half * 8;
                float v0 = acc[mf][nf][half * 2];
                float v1 = acc[mf][nf][half * 2 + 1];
                size_t o = (rbase + row) * DIM + col;
                *reinterpret_cast<__half2*>(dst0 + o) =
                    __halves2half2(__float2half_rn(v0), __float2half_rn(v1));
            }
        }
    }
}

// Scores + exp + per-tile row sums. Compact triangular grid: (528 pairs, 4 b).
__global__ __launch_bounds__(NTHR) void scores_kernel() {
    const int l = blockIdx.x;
    int qt = (int)((sqrtf(8.f * (float)l + 1.f) - 1.f) * 0.5f);
    while ((qt + 1) * (qt + 2) / 2 <= l) ++qt;
    while (qt * (qt + 1) / 2 > l) --qt;
    const int kt = l - qt * (qt + 1) / 2;
    const int b = blockIdx.y;

    const size_t qoff = ((size_t)b * SEQ + (size_t)qt * 128) * DIM;
    const size_t koff = ((size_t)b * SEQ + (size_t)kt * 128) * DIM;

    float acc[4][4][4];
    gemm_fp16(g_Qf + qoff, DIM, g_Kf + koff, DIM, DIM, acc);

    const int lane = threadIdx.x & 31, wid = threadIdx.x >> 5;
    const int wm = wid >> 2, wn = wid & 3;
    const int g = lane >> 2, t = lane & 3;
    const float scale = 0.04419417382415922f;   // 1/sqrt(512)

    float rowpart[4][2];
#pragma unroll
    for (int mf = 0; mf < 4; ++mf) { rowpart[mf][0] = 0.f; rowpart[mf][1] = 0.f; }

#pragma unroll
    for (int mf = 0; mf < 4; ++mf) {
#pragma unroll
        for (int nf = 0; nf < 4; ++nf) {
            const int col = kt * 128 + wn * 32 + nf * 8 + 2 * t;
#pragma unroll
            for (int half = 0; half < 2; ++half) {
                const int lrow = wm * 64 + mf * 16 + g + half * 8;
                const int qrow = qt * 128 + lrow;
                float e0 = (col     <= qrow) ? __expf(acc[mf][nf][half * 2]     * scale) : 0.f;
                float e1 = (col + 1 <= qrow) ? __expf(acc[mf][nf][half * 2 + 1] * scale) : 0.f;
                rowpart[mf][half] += e0 + e1;
                __half* dst = g_Ph + ((size_t)b * SEQ + qrow) * SEQ + col;
                *reinterpret_cast<__half2*>(dst) =
                    __halves2half2(__float2half_rn(e0), __float2half_rn(e1));
            }
        }
    }

    extern __shared__ char rawsm[];
    float (*spart)[4] = reinterpret_cast<float (*)[4]>(rawsm);  // [128][4]

#pragma unroll
    for (int mf = 0; mf < 4; ++mf)
#pragma unroll
        for (int half = 0; half < 2; ++half) {
            float r = rowpart[mf][half];
            r += __shfl_xor_sync(0xffffffffu, r, 1);
            r += __shfl_xor_sync(0xffffffffu, r, 2);
            if (t == 0) spart[wm * 64 + mf * 16 + g + half * 8][wn] = r;
        }
    __syncthreads();

    if (threadIdx.x < 128) {
        const int lrow = threadIdx.x;
        float L = (spart[lrow][0] + spart[lrow][1]) + (spart[lrow][2] + spart[lrow][3]);
        g_Lpart[(((size_t)(b * 32 + qt)) * 128 + lrow) * 32 + kt] = L;
    }
}

// PV split-K: grid (80 split-jobs, 4 nt, 4 b). Each CTA handles <=16 K-chunks
// (1024 keys) and writes an UNNORMALIZED fp32 partial tile to g_Opart.
// x index reversed -> heaviest (full 16-chunk) splits launch first.
__global__ __launch_bounds__(NTHR) void pv_kernel() {
    const int s  = 79 - blockIdx.x;
    const int nt = blockIdx.y, b = blockIdx.z;

    // decode split-job s -> (qt, split); nsplit(qt) = qt/8 + 1
    int qt = 0, base = 0;
    while (base + ((qt >> 3) + 1) <= s) { base += (qt >> 3) + 1; ++qt; }
    const int split = s - base;

    const int kmax = (qt + 1) * 128;
    const int k0 = split * 1024;
    const int k1 = (k0 + 1024 < kmax) ? (k0 + 1024) : kmax;

    const size_t poff = ((size_t)b * SEQ + (size_t)qt * 128) * SEQ;
    const __half* Vb = g_Vf + (size_t)b * SEQ * DIM + nt * 128;

    float acc[4][4][4];
    gemm_fp16_pv(g_Ph + poff + k0, SEQ, Vb + (size_t)k0 * DIM, k1 - k0, acc);

    const int lane = threadIdx.x & 31, wid = threadIdx.x >> 5;
    const int wm = wid >> 2, wn = wid & 3;
    const int g = lane >> 2, t = lane & 3;

    float* pdst = g_Opart + ((size_t)((b * 4 + nt) * 80 + s)) * 16384;

#pragma unroll
    for (int mf = 0; mf < 4; ++mf) {
#pragma unroll
        for (int half = 0; half < 2; ++half) {
            const int lrow = wm * 64 + mf * 16 + g + half * 8;
#pragma unroll
            for (int nf = 0; nf < 4; ++nf) {
                const int lcol = wn * 32 + nf * 8 + 2 * t;
                *reinterpret_cast<float2*>(pdst + lrow * 128 + lcol) =
                    make_float2(acc[mf][nf][half * 2], acc[mf][nf][half * 2 + 1]);
            }
        }
    }
}

// Combine: sum <=4 partials per tile, normalize by row sums, write out.
// grid (4 nt, 32 qt, 4 b), 256 threads; thread covers half a row (64 floats).
__global__ __launch_bounds__(256) void combine_kernel(float* __restrict__ out) {
    const int nt = blockIdx.x, qt = blockIdx.y, b = blockIdx.z;

    int base = 0;
    for (int q = 0; q < qt; ++q) base += (q >> 3) + 1;
    const int nsp = (qt >> 3) + 1;

    __shared__ float Ls[128];
    if (threadIdx.x < 128) {
        const float* Lp = g_Lpart + ((size_t)(b * 32 + qt)) * 128 * 32 + threadIdx.x * 32;
        float L = 0.f;
        for (int k = 0; k <= qt; ++k) L += Lp[k];
        Ls[threadIdx.x] = 1.0f / L;
    }
    __syncthreads();

    const int row = threadIdx.x >> 1;
    const int c0  = (threadIdx.x & 1) * 64;
    const float inv = Ls[row];
    const size_t pbase = ((size_t)((b * 4 + nt) * 80 + base)) * 16384 + row * 128 + c0;
    float* dst = out + ((size_t)b * SEQ + qt * 128 + row) * DIM + nt * 128 + c0;

#pragma unroll 4
    for (int j = 0; j < 16; ++j) {
        float4 a = *reinterpret_cast<const float4*>(g_Opart + pbase + j * 4);
        for (int sp = 1; sp < nsp; ++sp) {
            float4 p = *reinterpret_cast<const float4*>(g_Opart + pbase + (size_t)sp * 16384 + j * 4);
            a.x += p.x; a.y += p.y; a.z += p.z; a.w += p.w;
        }
        a.x *= inv; a.y *= inv; a.z *= inv; a.w *= inv;
        *reinterpret_cast<float4*>(dst + j * 4) = a;
    }
}

// ---------------- launch ----------------
extern "C" void kernel_launch(void* const* d_in, const int* in_sizes, int n_in,
                              void* d_out, int out_size)
{
    const float* x  = (const float*)d_in[0];
    const float* WQ = (const float*)d_in[1];
    const float* WK = (const float*)d_in[2];
    const float* WV = (const float*)d_in[3];
    float* out = (float*)d_out;

    cudaFuncSetAttribute(proj_kernel,   cudaFuncAttributeMaxDynamicSharedMemorySize, SMEM_ALLOC3);
    cudaFuncSetAttribute(scores_kernel, cudaFuncAttributeMaxDynamicSharedMemorySize, SMEM_ALLOC3);
    cudaFuncSetAttribute(pv_kernel,     cudaFuncAttributeMaxDynamicSharedMemorySize, SMEM_ALLOCP);

    convert_kernel<<<2240, 1024>>>(x, WQ, WK, WV);

    proj_kernel<<<dim3(4, 128, 3), NTHR, SMEM_ALLOC3>>>();

    scores_kernel<<<dim3(528, 4), NTHR, SMEM_ALLOC3>>>();

    pv_kernel<<<dim3(80, 4, 4), NTHR, SMEM_ALLOCP>>>();

    combine_kernel<<<dim3(4, 32, 4), 256>>>(out);
}

// round 16
// speedup vs baseline: 1.0238x; 1.0238x over previous
#include <cuda_runtime.h>
#include <cuda_fp16.h>
#include <cstdint>

#define BATCH 4
#define SEQ   4096
#define DIM   512

#define NSD (4ull*4096ull*512ull)     // 8,388,608
#define NW  (3ull*512ull*512ull)      // 786,432
#define NSS (4ull*4096ull*4096ull)    // 67,108,864

// ---------------- static scratch (allocation-free) ----------------
__device__ __half g_Xf[NSD];                 // X plain fp16
__device__ __half g_Wf[NW];                  // weights plain fp16
__device__ __half g_Qf[NSD];
__device__ __half g_Kf[NSD];
__device__ __half g_Vf[NSD];
__device__ __half g_Ph[NSS];                 // unnormalized exp(scores), fp16
__device__ float  g_Lpart[(size_t)BATCH * 32 * 128 * 32];     // [b][qt][row][kt], 2 MB
__device__ float  g_Opart[(size_t)16 * 80 * 16384];           // [b*4+nt][s][128x128], 84 MB
__device__ int    g_cnt[(size_t)BATCH * 4 * 32];              // split arrival counters (zero-init)

// ---------------- PTX helpers (compute_103-baseline ISA only) ----------------
__device__ __forceinline__ uint32_t smem_u32(const void* p) {
    uint32_t a;
    asm("{ .reg .u64 t; cvta.to.shared.u64 t, %1; cvt.u32.u64 %0, t; }" : "=r"(a) : "l"(p));
    return a;
}

__device__ __forceinline__ void cp16(uint32_t s, const void* g) {
    asm volatile("cp.async.cg.shared.global [%0], [%1], 16;" :: "r"(s), "l"(g) : "memory");
}
#define CP_COMMIT() asm volatile("cp.async.commit_group;" ::: "memory")
#define CP_WAIT(n)  asm volatile("cp.async.wait_group %0;" :: "n"(n) : "memory")

__device__ __forceinline__ void ldm4(uint32_t addr, uint32_t r[4]) {
    asm volatile("ldmatrix.sync.aligned.m8n8.x4.shared.b16 {%0,%1,%2,%3}, [%4];"
                 : "=r"(r[0]), "=r"(r[1]), "=r"(r[2]), "=r"(r[3]) : "r"(addr));
}

__device__ __forceinline__ void ldm4t(uint32_t addr, uint32_t r[4]) {
    asm volatile("ldmatrix.sync.aligned.m8n8.x4.trans.shared.b16 {%0,%1,%2,%3}, [%4];"
                 : "=r"(r[0]), "=r"(r[1]), "=r"(r[2]), "=r"(r[3]) : "r"(addr));
}

__device__ __forceinline__ void mma_hf(float* c, const uint32_t* a, uint32_t b0, uint32_t b1) {
    asm volatile(
        "mma.sync.aligned.m16n8k16.row.col.f32.f16.f16.f32 "
        "{%0,%1,%2,%3}, {%4,%5,%6,%7}, {%8,%9}, {%0,%1,%2,%3};"
        : "+f"(c[0]), "+f"(c[1]), "+f"(c[2]), "+f"(c[3])
        : "r"(a[0]), "r"(a[1]), "r"(a[2]), "r"(a[3]), "r"(b0), "r"(b1));
}

// ---------------- GEMM config ----------------
#define ROWP     144
#define TILE_B   (128 * ROWP)          // 18432
#define ROWB     272
#define TILE_BB  (64 * ROWB)           // 17408
#define OFF3_A   0
#define OFF3_B   (1 * TILE_B)
#define STAGE3_B (2 * TILE_B)          // 36864
#define SMEM_ALLOC3 (2 * STAGE3_B)     // 73728
#define OFFP_A   0
#define OFFP_B   TILE_B
#define STAGEP_B (TILE_B + TILE_BB)    // 35840
#define SMEM_ALLOCP (2 * STAGEP_B)     // 71680
#define NTHR     256

template <typename T>
__device__ __forceinline__ void fill_tile(uint32_t sb, const T* __restrict__ src,
                                          int ld, int k0, int tid) {
#pragma unroll
    for (int v = 0; v < 4; ++v) {
        int idx = v * NTHR + tid;
        int row = idx >> 3;
        int c16 = idx & 7;
        cp16(sb + row * ROWP + c16 * 16, src + (size_t)row * ld + k0 + c16 * 8);
    }
}

__device__ __forceinline__ void fill_vtile(uint32_t sb, const __half* __restrict__ src,
                                           int k0, int tid) {
#pragma unroll
    for (int v = 0; v < 4; ++v) {
        int idx = v * NTHR + tid;
        int row = idx >> 4;
        int c16 = idx & 15;
        cp16(sb + row * ROWB + c16 * 16, src + (size_t)(k0 + row) * DIM + c16 * 8);
    }
}

// ---------------- plain fp16 mainloop (proj & scores) ----------------
__device__ __forceinline__ void gemm_fp16(
    const __half* __restrict__ A, int lda,
    const __half* __restrict__ B, int ldb,
    int ktotal, float acc[4][4][4])
{
    extern __shared__ char rawsm[];
    const uint32_t smb = smem_u32(rawsm);
    const int tid  = threadIdx.x;
    const int lane = tid & 31;
    const int wid  = tid >> 5;
    const int wm   = wid >> 2;
    const int wn   = wid & 3;

#pragma unroll
    for (int i = 0; i < 4; ++i)
#pragma unroll
        for (int j = 0; j < 4; ++j)
#pragma unroll
            for (int k = 0; k < 4; ++k) acc[i][j][k] = 0.f;

    const int nch = ktotal >> 6;

    fill_tile(smb + OFF3_A, A, lda, 0, tid);
    fill_tile(smb + OFF3_B, B, ldb, 0, tid);
    CP_COMMIT();

    const uint32_t a_row_off = (uint32_t)((wm * 64 + (lane & 15)) * ROWP);
    const uint32_t b_row_off = (uint32_t)((wn * 32 + (lane & 7) + ((lane >> 3) & 1) * 8) * ROWP);
    const uint32_t k_half    = (uint32_t)(((lane >> 4) & 1) * 16);

    for (int c = 0; c < nch; ++c) {
        CP_WAIT(0);
        __syncthreads();
        if (c + 1 < nch) {
            const uint32_t nb = smb + (uint32_t)(((c + 1) & 1) * STAGE3_B);
            const int nk = (c + 1) << 6;
            fill_tile(nb + OFF3_A, A, lda, nk, tid);
            fill_tile(nb + OFF3_B, B, ldb, nk, tid);
            CP_COMMIT();
        }

        const uint32_t sb = smb + (uint32_t)((c & 1) * STAGE3_B);

#pragma unroll
        for (int ks = 0; ks < 4; ++ks) {
            const uint32_t ko = (uint32_t)(ks * 32) + k_half;

            uint32_t ra[4][4], rb[2][4];
#pragma unroll
            for (int mf = 0; mf < 4; ++mf)
                ldm4(sb + OFF3_A + a_row_off + (uint32_t)(mf * 16 * ROWP) + ko, ra[mf]);
#pragma unroll
            for (int bf = 0; bf < 2; ++bf)
                ldm4(sb + OFF3_B + b_row_off + (uint32_t)(bf * 16 * ROWP) + ko, rb[bf]);

#pragma unroll
            for (int mf = 0; mf < 4; ++mf)
#pragma unroll
                for (int bf = 0; bf < 2; ++bf) {
                    mma_hf(acc[mf][bf * 2],     ra[mf], rb[bf][0], rb[bf][2]);
                    mma_hf(acc[mf][bf * 2 + 1], ra[mf], rb[bf][1], rb[bf][3]);
                }
        }
    }
    __syncthreads();
}

// ---------------- pv mainloop: B from natural V via ldmatrix.trans ----------
__device__ __forceinline__ void gemm_fp16_pv(
    const __half* __restrict__ A, int lda,
    const __half* __restrict__ V,
    int ktotal, float acc[4][4][4])
{
    extern __shared__ char rawsm[];
    const uint32_t smb = smem_u32(rawsm);
    const int tid  = threadIdx.x;
    const int lane = tid & 31;
    const int wid  = tid >> 5;
    const int wm   = wid >> 2;
    const int wn   = wid & 3;

#pragma unroll
    for (int i = 0; i < 4; ++i)
#pragma unroll
        for (int j = 0; j < 4; ++j)
#pragma unroll
            for (int k = 0; k < 4; ++k) acc[i][j][k] = 0.f;

    const int nch = ktotal >> 6;

    fill_tile(smb + OFFP_A, A, lda, 0, tid);
    fill_vtile(smb + OFFP_B, V, 0, tid);
    CP_COMMIT();

    const uint32_t a_row_off = (uint32_t)((wm * 64 + (lane & 15)) * ROWP);
    const uint32_t k_half    = (uint32_t)(((lane >> 4) & 1) * 16);
    const uint32_t bt_off = (uint32_t)(((lane & 7) + ((lane >> 4) & 1) * 8) * ROWB
                                       + wn * 64 + ((lane >> 3) & 1) * 16);

    for (int c = 0; c < nch; ++c) {
        CP_WAIT(0);
        __syncthreads();
        if (c + 1 < nch) {
            const uint32_t nb = smb + (uint32_t)(((c + 1) & 1) * STAGEP_B);
            const int nk = (c + 1) << 6;
            fill_tile(nb + OFFP_A, A, lda, nk, tid);
            fill_vtile(nb + OFFP_B, V, nk, tid);
            CP_COMMIT();
        }

        const uint32_t sb = smb + (uint32_t)((c & 1) * STAGEP_B);

#pragma unroll
        for (int ks = 0; ks < 4; ++ks) {
            const uint32_t ko = (uint32_t)(ks * 32) + k_half;

            uint32_t ra[4][4], rb[2][4];
#pragma unroll
            for (int mf = 0; mf < 4; ++mf)
                ldm4(sb + OFFP_A + a_row_off + (uint32_t)(mf * 16 * ROWP) + ko, ra[mf]);
#pragma unroll
            for (int bf = 0; bf < 2; ++bf)
                ldm4t(sb + OFFP_B + (uint32_t)(ks * 16 * ROWB) + bt_off + (uint32_t)(bf * 32),
                      rb[bf]);

#pragma unroll
            for (int mf = 0; mf < 4; ++mf)
#pragma unroll
                for (int bf = 0; bf < 2; ++bf) {
                    mma_hf(acc[mf][bf * 2],     ra[mf], rb[bf][0], rb[bf][2]);
                    mma_hf(acc[mf][bf * 2 + 1], ra[mf], rb[bf][1], rb[bf][3]);
                }
        }
    }
    __syncthreads();
}

// ---------------- stage kernels ----------------

// X and W -> plain fp16, vectorized 4-wide, one launch
__global__ __launch_bounds__(1024) void convert_kernel(const float* __restrict__ x,
                                                       const float* __restrict__ wq,
                                                       const float* __restrict__ wk,
                                                       const float* __restrict__ wv) {
    size_t i = (size_t)blockIdx.x * blockDim.x + threadIdx.x;   // float4 index
    const size_t nx4 = NSD >> 2, nw4 = NW >> 2, nwq4 = (NW / 3) >> 2;
    if (i < nx4) {
        float4 v = reinterpret_cast<const float4*>(x)[i];
        __half2 h0 = __halves2half2(__float2half_rn(v.x), __float2half_rn(v.y));
        __half2 h1 = __halves2half2(__float2half_rn(v.z), __float2half_rn(v.w));
        reinterpret_cast<__half2*>(g_Xf)[i * 2]     = h0;
        reinterpret_cast<__half2*>(g_Xf)[i * 2 + 1] = h1;
    } else if (i < nx4 + nw4) {
        size_t j = i - nx4;
        size_t which = j / nwq4;
        size_t off   = j - which * nwq4;
        const float* src = (which == 0) ? wq : (which == 1) ? wk : wv;
        float4 v = reinterpret_cast<const float4*>(src)[off];
        __half2 h0 = __halves2half2(__float2half_rn(v.x), __float2half_rn(v.y));
        __half2 h1 = __halves2half2(__float2half_rn(v.z), __float2half_rn(v.w));
        reinterpret_cast<__half2*>(g_Wf)[j * 2]     = h0;
        reinterpret_cast<__half2*>(g_Wf)[j * 2 + 1] = h1;
    }
}

// QKV projection: grid (4 ntile, 128 mtile, 3 which)
__global__ __launch_bounds__(NTHR) void proj_kernel() {
    const int nt = blockIdx.x, mt = blockIdx.y, z = blockIdx.z;
    const __half* A = g_Xf + (size_t)mt * 128 * DIM;
    const __half* B = g_Wf + (size_t)z * DIM * DIM + (size_t)nt * 128 * DIM;

    float acc[4][4][4];
    gemm_fp16(A, DIM, B, DIM, DIM, acc);

    __half* dst0 = (z == 0) ? g_Qf : (z == 1) ? g_Kf : g_Vf;

    const int lane = threadIdx.x & 31, wid = threadIdx.x >> 5;
    const int wm = wid >> 2, wn = wid & 3;
    const int g = lane >> 2, t = lane & 3;
    const size_t rbase = (size_t)mt * 128;
    const int cbase = nt * 128 + wn * 32 + 2 * t;

#pragma unroll
    for (int mf = 0; mf < 4; ++mf) {
#pragma unroll
        for (int nf = 0; nf < 4; ++nf) {
            const int col = cbase + nf * 8;
#pragma unroll
            for (int half = 0; half < 2; ++half) {
                const int row = wm * 64 + mf * 16 + g + half * 8;
                float v0 = acc[mf][nf][half * 2];
                float v1 = acc[mf][nf][half * 2 + 1];
                size_t o = (rbase + row) * DIM + col;
                *reinterpret_cast<__half2*>(dst0 + o) =
                    __halves2half2(__float2half_rn(v0), __float2half_rn(v1));
            }
        }
    }
}

// Scores + exp + per-tile row sums. Compact triangular grid: (528 pairs, 4 b).
__global__ __launch_bounds__(NTHR) void scores_kernel() {
    const int l = blockIdx.x;
    int qt = (int)((sqrtf(8.f * (float)l + 1.f) - 1.f) * 0.5f);
    while ((qt + 1) * (qt + 2) / 2 <= l) ++qt;
    while (qt * (qt + 1) / 2 > l) --qt;
    const int kt = l - qt * (qt + 1) / 2;
    const int b = blockIdx.y;

    const size_t qoff = ((size_t)b * SEQ + (size_t)qt * 128) * DIM;
    const size_t koff = ((size_t)b * SEQ + (size_t)kt * 128) * DIM;

    float acc[4][4][4];
    gemm_fp16(g_Qf + qoff, DIM, g_Kf + koff, DIM, DIM, acc);

    const int lane = threadIdx.x & 31, wid = threadIdx.x >> 5;
    const int wm = wid >> 2, wn = wid & 3;
    const int g = lane >> 2, t = lane & 3;
    const float scale = 0.04419417382415922f;   // 1/sqrt(512)

    float rowpart[4][2];
#pragma unroll
    for (int mf = 0; mf < 4; ++mf) { rowpart[mf][0] = 0.f; rowpart[mf][1] = 0.f; }

#pragma unroll
    for (int mf = 0; mf < 4; ++mf) {
#pragma unroll
        for (int nf = 0; nf < 4; ++nf) {
            const int col = kt * 128 + wn * 32 + nf * 8 + 2 * t;
#pragma unroll
            for (int half = 0; half < 2; ++half) {
                const int lrow = wm * 64 + mf * 16 + g + half * 8;
                const int qrow = qt * 128 + lrow;
                float e0 = (col     <= qrow) ? __expf(acc[mf][nf][half * 2]     * scale) : 0.f;
                float e1 = (col + 1 <= qrow) ? __expf(acc[mf][nf][half * 2 + 1] * scale) : 0.f;
                rowpart[mf][half] += e0 + e1;
                __half* dst = g_Ph + ((size_t)b * SEQ + qrow) * SEQ + col;
                *reinterpret_cast<__half2*>(dst) =
                    __halves2half2(__float2half_rn(e0), __float2half_rn(e1));
            }
        }
    }

    extern __shared__ char rawsm[];
    float (*spart)[4] = reinterpret_cast<float (*)[4]>(rawsm);  // [128][4]

#pragma unroll
    for (int mf = 0; mf < 4; ++mf)
#pragma unroll
        for (int half = 0; half < 2; ++half) {
            float r = rowpart[mf][half];
            r += __shfl_xor_sync(0xffffffffu, r, 1);
            r += __shfl_xor_sync(0xffffffffu, r, 2);
            if (t == 0) spart[wm * 64 + mf * 16 + g + half * 8][wn] = r;
        }
    __syncthreads();

    if (threadIdx.x < 128) {
        const int lrow = threadIdx.x;
        float L = (spart[lrow][0] + spart[lrow][1]) + (spart[lrow][2] + spart[lrow][3]);
        g_Lpart[(((size_t)(b * 32 + qt)) * 128 + lrow) * 32 + kt] = L;
    }
}

// PV split-K with fused finalize. grid (80 split-jobs, 4 nt, 4 b).
// Each CTA computes <=16 K-chunks. nsp==1 tiles finalize directly from regs.
// Multi-split tiles: write fp32 partial, arrive on a counter; the LAST CTA
// re-reads ALL nsp partials in fixed sp order (order-independent of arrival),
// normalizes by L, writes out, and resets the counter (graph-replay safe).
__global__ __launch_bounds__(NTHR) void pv_kernel(float* __restrict__ out) {
    const int s  = 79 - blockIdx.x;
    const int nt = blockIdx.y, b = blockIdx.z;

    // decode split-job s -> (qt, split); nsplit(qt) = qt/8 + 1; base = first job of qt
    int qt = 0, base = 0;
    while (base + ((qt >> 3) + 1) <= s) { base += (qt >> 3) + 1; ++qt; }
    const int split = s - base;
    const int nsp = (qt >> 3) + 1;

    const int kmax = (qt + 1) * 128;
    const int k0 = split * 1024;
    const int k1 = (k0 + 1024 < kmax) ? (k0 + 1024) : kmax;

    const size_t poff = ((size_t)b * SEQ + (size_t)qt * 128) * SEQ;
    const __half* Vb = g_Vf + (size_t)b * SEQ * DIM + nt * 128;

    float acc[4][4][4];
    gemm_fp16_pv(g_Ph + poff + k0, SEQ, Vb + (size_t)k0 * DIM, k1 - k0, acc);

    const int lane = threadIdx.x & 31, wid = threadIdx.x >> 5;
    const int wm = wid >> 2, wn = wid & 3;
    const int g = lane >> 2, t = lane & 3;

    const float* Lp = g_Lpart + ((size_t)(b * 32 + qt)) * 128 * 32;
    const int cidx = (b * 4 + nt) * 32 + qt;

    if (nsp == 1) {
        // single split: finalize directly from registers
#pragma unroll
        for (int mf = 0; mf < 4; ++mf) {
#pragma unroll
            for (int half = 0; half < 2; ++half) {
                const int lrow = wm * 64 + mf * 16 + g + half * 8;
                float L = 0.f;
                for (int k = 0; k <= qt; ++k) L += Lp[lrow * 32 + k];
                const float inv = 1.0f / L;
                const int row = qt * 128 + lrow;
#pragma unroll
                for (int nf = 0; nf < 4; ++nf) {
                    const int col = nt * 128 + wn * 32 + nf * 8 + 2 * t;
                    float* dst = out + ((size_t)b * SEQ + row) * DIM + col;
                    *reinterpret_cast<float2*>(dst) =
                        make_float2(acc[mf][nf][half * 2] * inv, acc[mf][nf][half * 2 + 1] * inv);
                }
            }
        }
        return;
    }

    // multi-split: write this CTA's partial
    float* pdst = g_Opart + ((size_t)((b * 4 + nt) * 80 + s)) * 16384;
#pragma unroll
    for (int mf = 0; mf < 4; ++mf) {
#pragma unroll
        for (int half = 0; half < 2; ++half) {
            const int lrow = wm * 64 + mf * 16 + g + half * 8;
#pragma unroll
            for (int nf = 0; nf < 4; ++nf) {
                const int lcol = wn * 32 + nf * 8 + 2 * t;
                *reinterpret_cast<float2*>(pdst + lrow * 128 + lcol) =
                    make_float2(acc[mf][nf][half * 2], acc[mf][nf][half * 2 + 1]);
            }
        }
    }
    __threadfence();
    __syncthreads();

    extern __shared__ char rawsm[];
    int* s_last = reinterpret_cast<int*>(rawsm);
    if (threadIdx.x == 0) {
        int old = atomicAdd(&g_cnt[cidx], 1);
        *s_last = (old == nsp - 1) ? 1 : 0;
    }
    __syncthreads();
    if (!*s_last) return;

    // last arriver: read all nsp partials in FIXED order, sum, normalize, write
    const float* pbase0 = g_Opart + ((size_t)((b * 4 + nt) * 80 + base)) * 16384;
#pragma unroll
    for (int mf = 0; mf < 4; ++mf) {
#pragma unroll
        for (int half = 0; half < 2; ++half) {
            const int lrow = wm * 64 + mf * 16 + g + half * 8;
            float L = 0.f;
            for (int k = 0; k <= qt; ++k) L += Lp[lrow * 32 + k];
            const float inv = 1.0f / L;
            const int row = qt * 128 + lrow;
#pragma unroll
            for (int nf = 0; nf < 4; ++nf) {
                const int lcol = wn * 32 + nf * 8 + 2 * t;
                float2 a = *reinterpret_cast<const float2*>(pbase0 + lrow * 128 + lcol);
                for (int sp = 1; sp < nsp; ++sp) {
                    float2 p = *reinterpret_cast<const float2*>(
                        pbase0 + (size_t)sp * 16384 + lrow * 128 + lcol);
                    a.x += p.x; a.y += p.y;
                }
                const int col = nt * 128 + lcol;
                float* dst = out + ((size_t)b * SEQ + row) * DIM + col;
                *reinterpret_cast<float2*>(dst) = make_float2(a.x * inv, a.y * inv);
            }
        }
    }
    __syncthreads();
    if (threadIdx.x == 0) g_cnt[cidx] = 0;   // reset for next graph replay
}

// ---------------- launch ----------------
extern "C" void kernel_launch(void* const* d_in, const int* in_sizes, int n_in,
                              void* d_out, int out_size)
{
    const float* x  = (const float*)d_in[0];
    const float* WQ = (const float*)d_in[1];
    const float* WK = (const float*)d_in[2];
    const float* WV = (const float*)d_in[3];
    float* out = (float*)d_out;

    cudaFuncSetAttribute(proj_kernel,   cudaFuncAttributeMaxDynamicSharedMemorySize, SMEM_ALLOC3);
    cudaFuncSetAttribute(scores_kernel, cudaFuncAttributeMaxDynamicSharedMemorySize, SMEM_ALLOC3);
    cudaFuncSetAttribute(pv_kernel,     cudaFuncAttributeMaxDynamicSharedMemorySize, SMEM_ALLOCP);

    convert_kernel<<<2240, 1024>>>(x, WQ, WK, WV);

    proj_kernel<<<dim3(4, 128, 3), NTHR, SMEM_ALLOC3>>>();

    scores_kernel<<<dim3(528, 4), NTHR, SMEM_ALLOC3>>>();

    pv_kernel<<<dim3(80, 4, 4), NTHR, SMEM_ALLOCP>>>(out);
}

// round 17
// speedup vs baseline: 1.0871x; 1.0618x over previous
#include <cuda_runtime.h>
#include <cuda_fp16.h>
#include <cstdint>

#define BATCH 4
#define SEQ   4096
#define DIM   512

#define NSD (4ull*4096ull*512ull)     // 8,388,608
#define NW  (3ull*512ull*512ull)      // 786,432
#define NSS (4ull*4096ull*4096ull)    // 67,108,864

// ---------------- static scratch (allocation-free) ----------------
__device__ __half g_Xf[NSD];                 // X plain fp16
__device__ __half g_Wf[NW];                  // weights plain fp16
__device__ __half g_Qf[NSD];
__device__ __half g_Kf[NSD];
__device__ __half g_Vf[NSD];
__device__ __half g_Ph[NSS];                 // unnormalized exp(scores), fp16
__device__ float  g_Lpart[(size_t)BATCH * 32 * 128 * 32];     // [b][qt][row][kt], 2 MB
__device__ float  g_invL[(size_t)BATCH * SEQ];                // per-row 1/L
__device__ float  g_Opart[(size_t)16 * 32 * 16384];           // [b*4+nt][(qt-16)*2+sp][128x128], 32 MB
__device__ int    g_cnt[256];                                 // per (b,nt,qt>=16) counters (zero-init)

// pv job table: 48 jobs, sorted by size (tiles) DESCENDING so big jobs start first.
// qt<16 -> nsp=1 single job; qt>=16 -> 2 splits.
__device__ const int8_t c_qt[48] = {15,30,31,31, 14,28,29,29,30, 13,26,27,27,28,
                                    12,24,25,25,26, 11,22,23,23,24, 10,20,21,21,22,
                                    9,18,19,19,20, 8,16,17,17,18, 7,16,
                                    6,5,4,3,2,1,0};
__device__ const int8_t c_sp[48] = {0,0,0,1, 0,0,0,1,1, 0,0,0,1,1,
                                    0,0,0,1,1, 0,0,0,1,1, 0,0,0,1,1,
                                    0,0,0,1,1, 0,0,0,1,1, 0,1,
                                    0,0,0,0,0,0,0};

// ---------------- PTX helpers (compute_103-baseline ISA only) ----------------
__device__ __forceinline__ uint32_t smem_u32(const void* p) {
    uint32_t a;
    asm("{ .reg .u64 t; cvta.to.shared.u64 t, %1; cvt.u32.u64 %0, t; }" : "=r"(a) : "l"(p));
    return a;
}

__device__ __forceinline__ void cp16(uint32_t s, const void* g) {
    asm volatile("cp.async.cg.shared.global [%0], [%1], 16;" :: "r"(s), "l"(g) : "memory");
}
#define CP_COMMIT() asm volatile("cp.async.commit_group;" ::: "memory")
#define CP_WAIT(n)  asm volatile("cp.async.wait_group %0;" :: "n"(n) : "memory")

__device__ __forceinline__ void ldm4(uint32_t addr, uint32_t r[4]) {
    asm volatile("ldmatrix.sync.aligned.m8n8.x4.shared.b16 {%0,%1,%2,%3}, [%4];"
                 : "=r"(r[0]), "=r"(r[1]), "=r"(r[2]), "=r"(r[3]) : "r"(addr));
}

__device__ __forceinline__ void ldm4t(uint32_t addr, uint32_t r[4]) {
    asm volatile("ldmatrix.sync.aligned.m8n8.x4.trans.shared.b16 {%0,%1,%2,%3}, [%4];"
                 : "=r"(r[0]), "=r"(r[1]), "=r"(r[2]), "=r"(r[3]) : "r"(addr));
}

__device__ __forceinline__ void mma_hf(float* c, const uint32_t* a, uint32_t b0, uint32_t b1) {
    asm volatile(
        "mma.sync.aligned.m16n8k16.row.col.f32.f16.f16.f32 "
        "{%0,%1,%2,%3}, {%4,%5,%6,%7}, {%8,%9}, {%0,%1,%2,%3};"
        : "+f"(c[0]), "+f"(c[1]), "+f"(c[2]), "+f"(c[3])
        : "r"(a[0]), "r"(a[1]), "r"(a[2]), "r"(a[3]), "r"(b0), "r"(b1));
}

// ---------------- GEMM config ----------------
#define ROWP     144
#define TILE_B   (128 * ROWP)          // 18432
#define ROWB     272
#define TILE_BB  (64 * ROWB)           // 17408
#define OFF3_A   0
#define OFF3_B   (1 * TILE_B)
#define STAGE3_B (2 * TILE_B)          // 36864
#define SMEM_ALLOC3 (2 * STAGE3_B)     // 73728
#define OFFP_A   0
#define OFFP_B   TILE_B
#define STAGEP_B (TILE_B + TILE_BB)    // 35840
#define SMEM_ALLOCP (2 * STAGEP_B)     // 71680
#define NTHR     256

template <typename T>
__device__ __forceinline__ void fill_tile(uint32_t sb, const T* __restrict__ src,
                                          int ld, int k0, int tid) {
#pragma unroll
    for (int v = 0; v < 4; ++v) {
        int idx = v * NTHR + tid;
        int row = idx >> 3;
        int c16 = idx & 7;
        cp16(sb + row * ROWP + c16 * 16, src + (size_t)row * ld + k0 + c16 * 8);
    }
}

__device__ __forceinline__ void fill_vtile(uint32_t sb, const __half* __restrict__ src,
                                           int k0, int tid) {
#pragma unroll
    for (int v = 0; v < 4; ++v) {
        int idx = v * NTHR + tid;
        int row = idx >> 4;
        int c16 = idx & 15;
        cp16(sb + row * ROWB + c16 * 16, src + (size_t)(k0 + row) * DIM + c16 * 8);
    }
}

// ---------------- plain fp16 mainloop (proj & scores) ----------------
__device__ __forceinline__ void gemm_fp16(
    const __half* __restrict__ A, int lda,
    const __half* __restrict__ B, int ldb,
    int ktotal, float acc[4][4][4])
{
    extern __shared__ char rawsm[];
    const uint32_t smb = smem_u32(rawsm);
    const int tid  = threadIdx.x;
    const int lane = tid & 31;
    const int wid  = tid >> 5;
    const int wm   = wid >> 2;
    const int wn   = wid & 3;

#pragma unroll
    for (int i = 0; i < 4; ++i)
#pragma unroll
        for (int j = 0; j < 4; ++j)
#pragma unroll
            for (int k = 0; k < 4; ++k) acc[i][j][k] = 0.f;

    const int nch = ktotal >> 6;

    fill_tile(smb + OFF3_A, A, lda, 0, tid);
    fill_tile(smb + OFF3_B, B, ldb, 0, tid);
    CP_COMMIT();

    const uint32_t a_row_off = (uint32_t)((wm * 64 + (lane & 15)) * ROWP);
    const uint32_t b_row_off = (uint32_t)((wn * 32 + (lane & 7) + ((lane >> 3) & 1) * 8) * ROWP);
    const uint32_t k_half    = (uint32_t)(((lane >> 4) & 1) * 16);

    for (int c = 0; c < nch; ++c) {
        CP_WAIT(0);
        __syncthreads();
        if (c + 1 < nch) {
            const uint32_t nb = smb + (uint32_t)(((c + 1) & 1) * STAGE3_B);
            const int nk = (c + 1) << 6;
            fill_tile(nb + OFF3_A, A, lda, nk, tid);
            fill_tile(nb + OFF3_B, B, ldb, nk, tid);
            CP_COMMIT();
        }

        const uint32_t sb = smb + (uint32_t)((c & 1) * STAGE3_B);

#pragma unroll
        for (int ks = 0; ks < 4; ++ks) {
            const uint32_t ko = (uint32_t)(ks * 32) + k_half;

            uint32_t ra[4][4], rb[2][4];
#pragma unroll
            for (int mf = 0; mf < 4; ++mf)
                ldm4(sb + OFF3_A + a_row_off + (uint32_t)(mf * 16 * ROWP) + ko, ra[mf]);
#pragma unroll
            for (int bf = 0; bf < 2; ++bf)
                ldm4(sb + OFF3_B + b_row_off + (uint32_t)(bf * 16 * ROWP) + ko, rb[bf]);

#pragma unroll
            for (int mf = 0; mf < 4; ++mf)
#pragma unroll
                for (int bf = 0; bf < 2; ++bf) {
                    mma_hf(acc[mf][bf * 2],     ra[mf], rb[bf][0], rb[bf][2]);
                    mma_hf(acc[mf][bf * 2 + 1], ra[mf], rb[bf][1], rb[bf][3]);
                }
        }
    }
    __syncthreads();
}

// ---------------- pv mainloop: B from natural V via ldmatrix.trans ----------
__device__ __forceinline__ void gemm_fp16_pv(
    const __half* __restrict__ A, int lda,
    const __half* __restrict__ V,
    int ktotal, float acc[4][4][4])
{
    extern __shared__ char rawsm[];
    const uint32_t smb = smem_u32(rawsm);
    const int tid  = threadIdx.x;
    const int lane = tid & 31;
    const int wid  = tid >> 5;
    const int wm   = wid >> 2;
    const int wn   = wid & 3;

#pragma unroll
    for (int i = 0; i < 4; ++i)
#pragma unroll
        for (int j = 0; j < 4; ++j)
#pragma unroll
            for (int k = 0; k < 4; ++k) acc[i][j][k] = 0.f;

    const int nch = ktotal >> 6;

    fill_tile(smb + OFFP_A, A, lda, 0, tid);
    fill_vtile(smb + OFFP_B, V, 0, tid);
    CP_COMMIT();

    const uint32_t a_row_off = (uint32_t)((wm * 64 + (lane & 15)) * ROWP);
    const uint32_t k_half    = (uint32_t)(((lane >> 4) & 1) * 16);
    const uint32_t bt_off = (uint32_t)(((lane & 7) + ((lane >> 4) & 1) * 8) * ROWB
                                       + wn * 64 + ((lane >> 3) & 1) * 16);

    for (int c = 0; c < nch; ++c) {
        CP_WAIT(0);
        __syncthreads();
        if (c + 1 < nch) {
            const uint32_t nb = smb + (uint32_t)(((c + 1) & 1) * STAGEP_B);
            const int nk = (c + 1) << 6;
            fill_tile(nb + OFFP_A, A, lda, nk, tid);
            fill_vtile(nb + OFFP_B, V, nk, tid);
            CP_COMMIT();
        }

        const uint32_t sb = smb + (uint32_t)((c & 1) * STAGEP_B);

#pragma unroll
        for (int ks = 0; ks < 4; ++ks) {
            const uint32_t ko = (uint32_t)(ks * 32) + k_half;

            uint32_t ra[4][4], rb[2][4];
#pragma unroll
            for (int mf = 0; mf < 4; ++mf)
                ldm4(sb + OFFP_A + a_row_off + (uint32_t)(mf * 16 * ROWP) + ko, ra[mf]);
#pragma unroll
            for (int bf = 0; bf < 2; ++bf)
                ldm4t(sb + OFFP_B + (uint32_t)(ks * 16 * ROWB) + bt_off + (uint32_t)(bf * 32),
                      rb[bf]);

#pragma unroll
            for (int mf = 0; mf < 4; ++mf)
#pragma unroll
                for (int bf = 0; bf < 2; ++bf) {
                    mma_hf(acc[mf][bf * 2],     ra[mf], rb[bf][0], rb[bf][2]);
                    mma_hf(acc[mf][bf * 2 + 1], ra[mf], rb[bf][1], rb[bf][3]);
                }
        }
    }
    __syncthreads();
}

// ---------------- stage kernels ----------------

// X and W -> plain fp16, vectorized 4-wide, one launch
__global__ __launch_bounds__(1024) void convert_kernel(const float* __restrict__ x,
                                                       const float* __restrict__ wq,
                                                       const float* __restrict__ wk,
                                                       const float* __restrict__ wv) {
    size_t i = (size_t)blockIdx.x * blockDim.x + threadIdx.x;   // float4 index
    const size_t nx4 = NSD >> 2, nw4 = NW >> 2, nwq4 = (NW / 3) >> 2;
    if (i < nx4) {
        float4 v = reinterpret_cast<const float4*>(x)[i];
        __half2 h0 = __halves2half2(__float2half_rn(v.x), __float2half_rn(v.y));
        __half2 h1 = __halves2half2(__float2half_rn(v.z), __float2half_rn(v.w));
        reinterpret_cast<__half2*>(g_Xf)[i * 2]     = h0;
        reinterpret_cast<__half2*>(g_Xf)[i * 2 + 1] = h1;
    } else if (i < nx4 + nw4) {
        size_t j = i - nx4;
        size_t which = j / nwq4;
        size_t off   = j - which * nwq4;
        const float* src = (which == 0) ? wq : (which == 1) ? wk : wv;
        float4 v = reinterpret_cast<const float4*>(src)[off];
        __half2 h0 = __halves2half2(__float2half_rn(v.x), __float2half_rn(v.y));
        __half2 h1 = __halves2half2(__float2half_rn(v.z), __float2half_rn(v.w));
        reinterpret_cast<__half2*>(g_Wf)[j * 2]     = h0;
        reinterpret_cast<__half2*>(g_Wf)[j * 2 + 1] = h1;
    }
}

// QKV projection: grid (4 ntile, 128 mtile, 3 which)
__global__ __launch_bounds__(NTHR) void proj_kernel() {
    const int nt = blockIdx.x, mt = blockIdx.y, z = blockIdx.z;
    const __half* A = g_Xf + (size_t)mt * 128 * DIM;
    const __half* B = g_Wf + (size_t)z * DIM * DIM + (size_t)nt * 128 * DIM;

    float acc[4][4][4];
    gemm_fp16(A, DIM, B, DIM, DIM, acc);

    __half* dst0 = (z == 0) ? g_Qf : (z == 1) ? g_Kf : g_Vf;

    const int lane = threadIdx.x & 31, wid = threadIdx.x >> 5;
    const int wm = wid >> 2, wn = wid & 3;
    const int g = lane >> 2, t = lane & 3;
    const size_t rbase = (size_t)mt * 128;
    const int cbase = nt * 128 + wn * 32 + 2 * t;

#pragma unroll
    for (int mf = 0; mf < 4; ++mf) {
#pragma unroll
        for (int nf = 0; nf < 4; ++nf) {
            const int col = cbase + nf * 8;
#pragma unroll
            for (int half = 0; half < 2; ++half) {
                const int row = wm * 64 + mf * 16 + g + half * 8;
                float v0 = acc[mf][nf][half * 2];
                float v1 = acc[mf][nf][half * 2 + 1];
                size_t o = (rbase + row) * DIM + col;
                *reinterpret_cast<__half2*>(dst0 + o) =
                    __halves2half2(__float2half_rn(v0), __float2half_rn(v1));
            }
        }
    }
}

// Scores + exp + per-tile row sums. Compact triangular grid: (528 pairs, 4 b).
__global__ __launch_bounds__(NTHR) void scores_kernel() {
    const int l = blockIdx.x;
    int qt = (int)((sqrtf(8.f * (float)l + 1.f) - 1.f) * 0.5f);
    while ((qt + 1) * (qt + 2) / 2 <= l) ++qt;
    while (qt * (qt + 1) / 2 > l) --qt;
    const int kt = l - qt * (qt + 1) / 2;
    const int b = blockIdx.y;

    const size_t qoff = ((size_t)b * SEQ + (size_t)qt * 128) * DIM;
    const size_t koff = ((size_t)b * SEQ + (size_t)kt * 128) * DIM;

    float acc[4][4][4];
    gemm_fp16(g_Qf + qoff, DIM, g_Kf + koff, DIM, DIM, acc);

    const int lane = threadIdx.x & 31, wid = threadIdx.x >> 5;
    const int wm = wid >> 2, wn = wid & 3;
    const int g = lane >> 2, t = lane & 3;
    const float scale = 0.04419417382415922f;   // 1/sqrt(512)

    float rowpart[4][2];
#pragma unroll
    for (int mf = 0; mf < 4; ++mf) { rowpart[mf][0] = 0.f; rowpart[mf][1] = 0.f; }

#pragma unroll
    for (int mf = 0; mf < 4; ++mf) {
#pragma unroll
        for (int nf = 0; nf < 4; ++nf) {
            const int col = kt * 128 + wn * 32 + nf * 8 + 2 * t;
#pragma unroll
            for (int half = 0; half < 2; ++half) {
                const int lrow = wm * 64 + mf * 16 + g + half * 8;
                const int qrow = qt * 128 + lrow;
                float e0 = (col     <= qrow) ? __expf(acc[mf][nf][half * 2]     * scale) : 0.f;
                float e1 = (col + 1 <= qrow) ? __expf(acc[mf][nf][half * 2 + 1] * scale) : 0.f;
                rowpart[mf][half] += e0 + e1;
                __half* dst = g_Ph + ((size_t)b * SEQ + qrow) * SEQ + col;
                *reinterpret_cast<__half2*>(dst) =
                    __halves2half2(__float2half_rn(e0), __float2half_rn(e1));
            }
        }
    }

    extern __shared__ char rawsm[];
    float (*spart)[4] = reinterpret_cast<float (*)[4]>(rawsm);  // [128][4]

#pragma unroll
    for (int mf = 0; mf < 4; ++mf)
#pragma unroll
        for (int half = 0; half < 2; ++half) {
            float r = rowpart[mf][half];
            r += __shfl_xor_sync(0xffffffffu, r, 1);
            r += __shfl_xor_sync(0xffffffffu, r, 2);
            if (t == 0) spart[wm * 64 + mf * 16 + g + half * 8][wn] = r;
        }
    __syncthreads();

    if (threadIdx.x < 128) {
        const int lrow = threadIdx.x;
        float L = (spart[lrow][0] + spart[lrow][1]) + (spart[lrow][2] + spart[lrow][3]);
        g_Lpart[(((size_t)(b * 32 + qt)) * 128 + lrow) * 32 + kt] = L;
    }
}

// Row-sum finalize: invL[b][s] = 1 / sum_{kt<=qt} Lpart (k ascending, same order
// as previous rounds -> bit-identical L). 16384 threads.
__global__ __launch_bounds__(256) void suml_kernel() {
    const int i = blockIdx.x * 256 + threadIdx.x;   // 0..16383
    const int b = i >> 12;
    const int r = i & 4095;
    const int qt = r >> 7;
    const int lrow = r & 127;
    const float* Lp = g_Lpart + (((size_t)(b * 32 + qt)) * 128 + lrow) * 32;
    float L = 0.f;
    for (int k = 0; k <= qt; ++k) L += Lp[k];
    g_invL[i] = 1.0f / L;
}

// PV split-K with fused finalize. grid (48 jobs, 4 nt, 4 b).
// Jobs from the descending-size table. qt<16: single CTA, finalize from regs.
// qt>=16: 2 splits; last arriver sums both partials in fixed order, normalizes.
__global__ __launch_bounds__(NTHR) void pv_kernel(float* __restrict__ out) {
    const int x  = blockIdx.x;
    const int qt = c_qt[x];
    const int split = c_sp[x];
    const int nt = blockIdx.y, b = blockIdx.z;
    const int nsp = (qt >= 16) ? 2 : 1;

    const int tiles = qt + 1;           // 128-key tiles
    const int t0 = (qt + 2) >> 1;       // split-0 tile count
    int k0, k1;
    if (nsp == 1) { k0 = 0; k1 = tiles * 128; }
    else { k0 = split ? t0 * 128 : 0; k1 = split ? tiles * 128 : t0 * 128; }

    const size_t poff = ((size_t)b * SEQ + (size_t)qt * 128) * SEQ;
    const __half* Vb = g_Vf + (size_t)b * SEQ * DIM + nt * 128;

    float acc[4][4][4];
    gemm_fp16_pv(g_Ph + poff + k0, SEQ, Vb + (size_t)k0 * DIM, k1 - k0, acc);

    const int lane = threadIdx.x & 31, wid = threadIdx.x >> 5;
    const int wm = wid >> 2, wn = wid & 3;
    const int g = lane >> 2, t = lane & 3;
    const float* invLrow = g_invL + (size_t)b * SEQ + qt * 128;

    if (nsp == 1) {
#pragma unroll
        for (int mf = 0; mf < 4; ++mf) {
#pragma unroll
            for (int half = 0; half < 2; ++half) {
                const int lrow = wm * 64 + mf * 16 + g + half * 8;
                const float inv = invLrow[lrow];
                const int row = qt * 128 + lrow;
#pragma unroll
                for (int nf = 0; nf < 4; ++nf) {
                    const int col = nt * 128 + wn * 32 + nf * 8 + 2 * t;
                    float* dst = out + ((size_t)b * SEQ + row) * DIM + col;
                    *reinterpret_cast<float2*>(dst) =
                        make_float2(acc[mf][nf][half * 2] * inv, acc[mf][nf][half * 2 + 1] * inv);
                }
            }
        }
        return;
    }

    // multi-split: write this CTA's partial
    const int pidx = (qt - 16) * 2 + split;
    float* pdst = g_Opart + ((size_t)((b * 4 + nt) * 32 + pidx)) * 16384;
#pragma unroll
    for (int mf = 0; mf < 4; ++mf) {
#pragma unroll
        for (int half = 0; half < 2; ++half) {
            const int lrow = wm * 64 + mf * 16 + g + half * 8;
#pragma unroll
            for (int nf = 0; nf < 4; ++nf) {
                const int lcol = wn * 32 + nf * 8 + 2 * t;
                *reinterpret_cast<float2*>(pdst + lrow * 128 + lcol) =
                    make_float2(acc[mf][nf][half * 2], acc[mf][nf][half * 2 + 1]);
            }
        }
    }
    __threadfence();
    __syncthreads();

    extern __shared__ char rawsm[];
    int* s_last = reinterpret_cast<int*>(rawsm);
    const int cidx = (b * 4 + nt) * 16 + (qt - 16);
    if (threadIdx.x == 0) {
        int old = atomicAdd(&g_cnt[cidx], 1);
        *s_last = (old == 1) ? 1 : 0;
    }
    __syncthreads();
    if (!*s_last) return;

    // last arriver: read both partials in FIXED order (sp0 then sp1), sum,
    // normalize, write out (order independent of which CTA finished last).
    const float* pbase0 = g_Opart + ((size_t)((b * 4 + nt) * 32 + (qt - 16) * 2)) * 16384;
#pragma unroll
    for (int mf = 0; mf < 4; ++mf) {
#pragma unroll
        for (int half = 0; half < 2; ++half) {
            const int lrow = wm * 64 + mf * 16 + g + half * 8;
            const float inv = invLrow[lrow];
            const int row = qt * 128 + lrow;
#pragma unroll
            for (int nf = 0; nf < 4; ++nf) {
                const int lcol = wn * 32 + nf * 8 + 2 * t;
                float2 a = *reinterpret_cast<const float2*>(pbase0 + lrow * 128 + lcol);
                float2 p = *reinterpret_cast<const float2*>(pbase0 + 16384 + lrow * 128 + lcol);
                a.x += p.x; a.y += p.y;
                const int col = nt * 128 + lcol;
                float* dst = out + ((size_t)b * SEQ + row) * DIM + col;
                *reinterpret_cast<float2*>(dst) = make_float2(a.x * inv, a.y * inv);
            }
        }
    }
    __syncthreads();
    if (threadIdx.x == 0) g_cnt[cidx] = 0;   // reset for next graph replay
}

// ---------------- launch ----------------
extern "C" void kernel_launch(void* const* d_in, const int* in_sizes, int n_in,
                              void* d_out, int out_size)
{
    const float* x  = (const float*)d_in[0];
    const float* WQ = (const float*)d_in[1];
    const float* WK = (const float*)d_in[2];
    const float* WV = (const float*)d_in[3];
    float* out = (float*)d_out;

    cudaFuncSetAttribute(proj_kernel,   cudaFuncAttributeMaxDynamicSharedMemorySize, SMEM_ALLOC3);
    cudaFuncSetAttribute(scores_kernel, cudaFuncAttributeMaxDynamicSharedMemorySize, SMEM_ALLOC3);
    cudaFuncSetAttribute(pv_kernel,     cudaFuncAttributeMaxDynamicSharedMemorySize, SMEM_ALLOCP);

    convert_kernel<<<2240, 1024>>>(x, WQ, WK, WV);

    proj_kernel<<<dim3(4, 128, 3), NTHR, SMEM_ALLOC3>>>();

    scores_kernel<<<dim3(528, 4), NTHR, SMEM_ALLOC3>>>();

    suml_kernel<<<64, 256>>>();

    pv_kernel<<<dim3(48, 4, 4), NTHR, SMEM_ALLOCP>>>(out);
}